// round 16
// baseline (speedup 1.0000x reference)
#include <cuda_runtime.h>
#include <cuda_bf16.h>
#include <cstdint>

#define SLAB 32768          // 64*512 floats per time slab
#define HS 516              // h row stride (floats), 16B-aligned
#define HSBUF (4 * HS)      // one h buffer (4 rows)
#define NSTEP 512

__device__ __forceinline__ void fma2(unsigned long long& d, unsigned long long a, unsigned long long b) {
    asm("fma.rn.f32x2 %0, %1, %2, %0;" : "+l"(d) : "l"(a), "l"(b));
}
__device__ __forceinline__ void add2(unsigned long long& d, unsigned long long a, unsigned long long b) {
    asm("add.rn.f32x2 %0, %1, %2;" : "=l"(d) : "l"(a), "l"(b));
}
__device__ __forceinline__ float2 u2f(unsigned long long v) {
    float2 r; asm("mov.b64 {%0, %1}, %2;" : "=f"(r.x), "=f"(r.y) : "l"(v)); return r;
}
__device__ __forceinline__ unsigned long long pack2(float x, float y) {
    unsigned long long d; asm("mov.b64 %0, {%1, %2};" : "=l"(d) : "f"(x), "f"(y)); return d;
}
__device__ __forceinline__ uint32_t smem_u32(const void* p) {
    uint32_t a;
    asm("{ .reg .u64 t; cvta.to.shared.u64 t, %1; cvt.u32.u64 %0, t; }" : "=r"(a) : "l"(p));
    return a;
}

// ---------------- Phase 1: out[t][b][u] = (x @ T)  ----------------
__global__ void __launch_bounds__(128) p1(const float* __restrict__ X,
                                          const float* __restrict__ T,
                                          float* __restrict__ out) {
    __shared__ float As[64 * 20];
    __shared__ float Ts[32 * 20];
    const int tid = threadIdx.x;
    const int rowBase = blockIdx.x * 64;
    const int n0 = blockIdx.y * 32;
    const int mq = tid >> 3;
    const int nq = tid & 7;

    unsigned long long acc[4][4];
#pragma unroll
    for (int i = 0; i < 4; ++i)
#pragma unroll
        for (int j = 0; j < 4; ++j) acc[i][j] = 0ull;

    for (int kb = 0; kb < 256; kb += 16) {
#pragma unroll
        for (int i2 = 0; i2 < 2; ++i2) {
            int q = tid + i2 * 128;
            int m = q >> 2, kq = (q & 3) * 4;
            *(float4*)&As[m * 20 + kq] = *(const float4*)&X[(rowBase + m) * 256 + kb + kq];
        }
        {
            int k = tid >> 3, n4 = (tid & 7) * 4;
            float4 v = *(const float4*)&T[(kb + k) * 512 + n0 + n4];
            Ts[(n4 + 0) * 20 + k] = v.x;
            Ts[(n4 + 1) * 20 + k] = v.y;
            Ts[(n4 + 2) * 20 + k] = v.z;
            Ts[(n4 + 3) * 20 + k] = v.w;
        }
        __syncthreads();
#pragma unroll
        for (int k = 0; k < 16; k += 4) {
            ulonglong2 a0 = *(const ulonglong2*)&As[(mq) * 20 + k];
            ulonglong2 a1 = *(const ulonglong2*)&As[(mq + 16) * 20 + k];
            ulonglong2 a2 = *(const ulonglong2*)&As[(mq + 32) * 20 + k];
            ulonglong2 a3 = *(const ulonglong2*)&As[(mq + 48) * 20 + k];
            ulonglong2 b0 = *(const ulonglong2*)&Ts[(nq) * 20 + k];
            ulonglong2 b1 = *(const ulonglong2*)&Ts[(nq + 8) * 20 + k];
            ulonglong2 b2 = *(const ulonglong2*)&Ts[(nq + 16) * 20 + k];
            ulonglong2 b3 = *(const ulonglong2*)&Ts[(nq + 24) * 20 + k];
            fma2(acc[0][0], a0.x, b0.x); fma2(acc[0][0], a0.y, b0.y);
            fma2(acc[0][1], a0.x, b1.x); fma2(acc[0][1], a0.y, b1.y);
            fma2(acc[0][2], a0.x, b2.x); fma2(acc[0][2], a0.y, b2.y);
            fma2(acc[0][3], a0.x, b3.x); fma2(acc[0][3], a0.y, b3.y);
            fma2(acc[1][0], a1.x, b0.x); fma2(acc[1][0], a1.y, b0.y);
            fma2(acc[1][1], a1.x, b1.x); fma2(acc[1][1], a1.y, b1.y);
            fma2(acc[1][2], a1.x, b2.x); fma2(acc[1][2], a1.y, b2.y);
            fma2(acc[1][3], a1.x, b3.x); fma2(acc[1][3], a1.y, b3.y);
            fma2(acc[2][0], a2.x, b0.x); fma2(acc[2][0], a2.y, b0.y);
            fma2(acc[2][1], a2.x, b1.x); fma2(acc[2][1], a2.y, b1.y);
            fma2(acc[2][2], a2.x, b2.x); fma2(acc[2][2], a2.y, b2.y);
            fma2(acc[2][3], a2.x, b3.x); fma2(acc[2][3], a2.y, b3.y);
            fma2(acc[3][0], a3.x, b0.x); fma2(acc[3][0], a3.y, b0.y);
            fma2(acc[3][1], a3.x, b1.x); fma2(acc[3][1], a3.y, b1.y);
            fma2(acc[3][2], a3.x, b2.x); fma2(acc[3][2], a3.y, b2.y);
            fma2(acc[3][3], a3.x, b3.x); fma2(acc[3][3], a3.y, b3.y);
        }
        __syncthreads();
    }
#pragma unroll
    for (int i = 0; i < 4; ++i) {
        int r = rowBase + mq + 16 * i;
        int tt = r & 511, bb = r >> 9;
        float* p = out + tt * SLAB + bb * 512 + n0 + nq;
#pragma unroll
        for (int j = 0; j < 4; ++j) {
            float2 v = u2f(acc[i][j]);
            p[8 * j] = v.x + v.y;
        }
    }
}

// ---------------- Phase 2: register-B + DSMEM-push recurrence --------------
// 16 clusters x 8 CTAs; cluster = 4 batch rows x 512 cols; CTA rank owns cols
// 64*rank. 256 thr = 8 warps (k-split 64); lane: 2 cols x 4 rows, B slice in
// 64 ull regs. h exchange: epilogue pushes outputs into ALL 8 CTAs' hs[t&1]
// via st.shared::cluster; ping-pong mbarriers (count 8). No L2 on the h path.
__global__ void __launch_bounds__(256, 1) p2(float* __restrict__ out,
                                             const float* __restrict__ B,
                                             const float* __restrict__ bias,
                                             const float* __restrict__ h0) {
    __shared__ float hs[2 * HSBUF];
    __shared__ unsigned long long red[256 * 9];
    __shared__ alignas(8) unsigned long long mbar_store[2];

    const int tid = threadIdx.x;
    const int w = tid >> 5, lane = tid & 31;
    uint32_t rank;
    asm("mov.u32 %0, %%cluster_ctarank;" : "=r"(rank));
    const int rowBase = (blockIdx.x >> 3) * 4;     // cluster id * 4 rows
    const int c0 = (int)rank * 64;
    const int kb = w * 64;
    const int col0 = c0 + 2 * lane;
    const int orow = tid >> 6, ocol = tid & 63;
    const float bia = bias[c0 + ocol];
    const uint32_t mbar0 = smem_u32(&mbar_store[0]);
    float* const outRC = out + (size_t)(rowBase + orow) * 512 + c0 + ocol;

    if (tid == 0) {
        asm volatile("mbarrier.init.shared.b64 [%0], %1;" :: "r"(mbar0),     "r"(8u) : "memory");
        asm volatile("mbarrier.init.shared.b64 [%0], %1;" :: "r"(mbar0 + 8), "r"(8u) : "memory");
    }

    // one-time: B slice into registers
    unsigned long long b0r[32], b1r[32];
#pragma unroll
    for (int j = 0; j < 32; ++j) {
        const float* p0 = B + (kb + 2 * j) * 512 + col0;
        b0r[j] = pack2(p0[0], p0[512]);
        b1r[j] = pack2(p0[1], p0[513]);
    }

    // preload h0 into hs buffer 1 (acts as "step -1" data)
#pragma unroll
    for (int i = 0; i < 2; ++i) {
        int u = tid + 256 * i;                 // 0..511 float4s
        int r = u >> 7, kq = (u & 127) * 4;
        *(float4*)&hs[HSBUF + r * HS + kq] = *(const float4*)(h0 + kq);
    }
    __syncthreads();
    // mbarrier init visible cluster-wide before any remote arrive
    asm volatile("barrier.cluster.arrive.aligned;" ::: "memory");
    asm volatile("barrier.cluster.wait.aligned;" ::: "memory");

    for (int t = 0; t < NSTEP; ++t) {
        float xv = __ldcg(outRC + (size_t)t * SLAB);   // xT term prefetch

        if (t > 0) {
            const uint32_t mb = mbar0 + ((t - 1) & 1) * 8;
            const unsigned int par = (unsigned int)(((t - 1) >> 1) & 1);
            asm volatile(
                "{\n\t.reg .pred P;\n"
                "W%=:\n\t"
                "mbarrier.try_wait.parity.shared.b64 P, [%0], %1, 0x989680;\n\t"
                "@P bra D%=;\n\t"
                "bra W%=;\n"
                "D%=:\n\t}"
                :: "r"(mb), "r"(par) : "memory");
            asm volatile("fence.acq_rel.cluster;" ::: "memory");  // acquire DSMEM pushes
        }
        __syncthreads();   // bar1: align threads; red reuse guard

        // compute from hs[(t-1)&1] (== hs[(t+1)&1]); broadcast LDS, B in regs
        const float* hb = hs + ((t + 1) & 1) * HSBUF;
        unsigned long long a00 = 0, a01 = 0, a10 = 0, a11 = 0;
        unsigned long long a20 = 0, a21 = 0, a30 = 0, a31 = 0;
#pragma unroll
        for (int i = 0; i < 16; ++i) {
            int k = kb + 4 * i;
            ulonglong2 h0v = *(const ulonglong2*)&hb[0 * HS + k];
            ulonglong2 h1v = *(const ulonglong2*)&hb[1 * HS + k];
            ulonglong2 h2v = *(const ulonglong2*)&hb[2 * HS + k];
            ulonglong2 h3v = *(const ulonglong2*)&hb[3 * HS + k];
            fma2(a00, h0v.x, b0r[2*i]); fma2(a00, h0v.y, b0r[2*i+1]);
            fma2(a01, h0v.x, b1r[2*i]); fma2(a01, h0v.y, b1r[2*i+1]);
            fma2(a10, h1v.x, b0r[2*i]); fma2(a10, h1v.y, b0r[2*i+1]);
            fma2(a11, h1v.x, b1r[2*i]); fma2(a11, h1v.y, b1r[2*i+1]);
            fma2(a20, h2v.x, b0r[2*i]); fma2(a20, h2v.y, b0r[2*i+1]);
            fma2(a21, h2v.x, b1r[2*i]); fma2(a21, h2v.y, b1r[2*i+1]);
            fma2(a30, h3v.x, b0r[2*i]); fma2(a30, h3v.y, b0r[2*i+1]);
            fma2(a31, h3v.x, b1r[2*i]); fma2(a31, h3v.y, b1r[2*i+1]);
        }

        red[(0 * 64 + 2 * lane) * 9 + w] = a00;  red[(0 * 64 + 2 * lane + 1) * 9 + w] = a01;
        red[(1 * 64 + 2 * lane) * 9 + w] = a10;  red[(1 * 64 + 2 * lane + 1) * 9 + w] = a11;
        red[(2 * 64 + 2 * lane) * 9 + w] = a20;  red[(2 * 64 + 2 * lane + 1) * 9 + w] = a21;
        red[(3 * 64 + 2 * lane) * 9 + w] = a30;  red[(3 * 64 + 2 * lane + 1) * 9 + w] = a31;
        __syncthreads();   // bar2: partials visible

        {
            const unsigned long long* rp = red + tid * 9;
            unsigned long long s = rp[0];
#pragma unroll
            for (int ww = 1; ww < 8; ++ww) add2(s, s, rp[ww]);
            float2 p = u2f(s);
            float z = p.x + p.y + xv;
            float a = fabsf(z) + bia;
            float r = (a > 0.f) ? copysignf(a, z) : 0.f;
            __stcg(outRC + (size_t)t * SLAB, r);          // final output
            if (t < NSTEP - 1) {
                // push h into all 8 CTAs' hs[t&1] (incl. self)
                uint32_t loc = smem_u32(&hs[(t & 1) * HSBUF + orow * HS]) + (uint32_t)(c0 + ocol) * 4u;
#pragma unroll
                for (int pr = 0; pr < 8; ++pr) {
                    asm volatile(
                        "{\n\t.reg .b32 ra;\n\t"
                        "mapa.shared::cluster.u32 ra, %0, %1;\n\t"
                        "st.shared::cluster.f32 [ra], %2;\n\t}"
                        :: "r"(loc), "r"(pr), "f"(r) : "memory");
                }
            }
        }
        __syncthreads();   // bar3: all pushes issued (hb before tid0 fence)
        if (t < NSTEP - 1 && tid == 0) {
            asm volatile("fence.acq_rel.cluster;" ::: "memory");  // release pushes
            const uint32_t mb = mbar0 + (t & 1) * 8;
#pragma unroll
            for (int pr = 0; pr < 8; ++pr) {
                asm volatile(
                    "{\n\t.reg .b32 ra;\n\t"
                    "mapa.shared::cluster.u32 ra, %0, %1;\n\t"
                    "mbarrier.arrive.shared::cluster.b64 _, [ra];\n\t}"
                    :: "r"(mb), "r"(pr) : "memory");
            }
        }
    }

    // exit guard: no CTA leaves while peer DSMEM ops may be in flight
    asm volatile("barrier.cluster.arrive.aligned;" ::: "memory");
    asm volatile("barrier.cluster.wait.aligned;" ::: "memory");
}

extern "C" void kernel_launch(void* const* d_in, const int* in_sizes, int n_in,
                              void* d_out, int out_size) {
    const float* x    = (const float*)d_in[0];
    const float* T    = (const float*)d_in[1];
    const float* B    = (const float*)d_in[2];
    const float* bias = (const float*)d_in[3];
    const float* h0   = (const float*)d_in[4];
    float* out = (float*)d_out;

    dim3 g1(512, 16);
    p1<<<g1, 128>>>(x, T, out);

    cudaLaunchConfig_t cfg = {};
    cfg.gridDim = dim3(128, 1, 1);
    cfg.blockDim = dim3(256, 1, 1);
    cfg.dynamicSmemBytes = 0;
    cfg.stream = 0;
    cudaLaunchAttribute attrs[1];
    attrs[0].id = cudaLaunchAttributeClusterDimension;
    attrs[0].val.clusterDim = {8, 1, 1};
    cfg.attrs = attrs;
    cfg.numAttrs = 1;
    cudaLaunchKernelEx(&cfg, p2, out, B, bias, h0);
}

// round 17
// speedup vs baseline: 1.6093x; 1.6093x over previous
#include <cuda_runtime.h>
#include <cuda_bf16.h>
#include <cstdint>

#define SLAB 32768          // 64*512 floats per time slab
#define HW 68               // per-warp h tile row stride (floats), 16B-aligned
#define NSTEP 512

__device__ unsigned int g_flag[1024];   // 128 flags padded to 32B

__device__ __forceinline__ void fma2(unsigned long long& d, unsigned long long a, unsigned long long b) {
    asm("fma.rn.f32x2 %0, %1, %2, %0;" : "+l"(d) : "l"(a), "l"(b));
}
__device__ __forceinline__ void add2(unsigned long long& d, unsigned long long a, unsigned long long b) {
    asm("add.rn.f32x2 %0, %1, %2;" : "=l"(d) : "l"(a), "l"(b));
}
__device__ __forceinline__ float2 u2f(unsigned long long v) {
    float2 r; asm("mov.b64 {%0, %1}, %2;" : "=f"(r.x), "=f"(r.y) : "l"(v)); return r;
}
__device__ __forceinline__ unsigned long long pack2(float x, float y) {
    unsigned long long d; asm("mov.b64 %0, {%1, %2};" : "=l"(d) : "f"(x), "f"(y)); return d;
}

// ---------------- Phase 1: out[t][b][u] = (x @ T)  ----------------
__global__ void __launch_bounds__(128) p1(const float* __restrict__ X,
                                          const float* __restrict__ T,
                                          float* __restrict__ out) {
    __shared__ float As[64 * 20];
    __shared__ float Ts[32 * 20];
    const int tid = threadIdx.x;
    if (blockIdx.x == 0 && blockIdx.y == 0) g_flag[tid * 8] = 0u;

    const int rowBase = blockIdx.x * 64;
    const int n0 = blockIdx.y * 32;
    const int mq = tid >> 3;
    const int nq = tid & 7;

    unsigned long long acc[4][4];
#pragma unroll
    for (int i = 0; i < 4; ++i)
#pragma unroll
        for (int j = 0; j < 4; ++j) acc[i][j] = 0ull;

    for (int kb = 0; kb < 256; kb += 16) {
#pragma unroll
        for (int i2 = 0; i2 < 2; ++i2) {
            int q = tid + i2 * 128;
            int m = q >> 2, kq = (q & 3) * 4;
            *(float4*)&As[m * 20 + kq] = *(const float4*)&X[(rowBase + m) * 256 + kb + kq];
        }
        {
            int k = tid >> 3, n4 = (tid & 7) * 4;
            float4 v = *(const float4*)&T[(kb + k) * 512 + n0 + n4];
            Ts[(n4 + 0) * 20 + k] = v.x;
            Ts[(n4 + 1) * 20 + k] = v.y;
            Ts[(n4 + 2) * 20 + k] = v.z;
            Ts[(n4 + 3) * 20 + k] = v.w;
        }
        __syncthreads();
#pragma unroll
        for (int k = 0; k < 16; k += 4) {
            ulonglong2 a0 = *(const ulonglong2*)&As[(mq) * 20 + k];
            ulonglong2 a1 = *(const ulonglong2*)&As[(mq + 16) * 20 + k];
            ulonglong2 a2 = *(const ulonglong2*)&As[(mq + 32) * 20 + k];
            ulonglong2 a3 = *(const ulonglong2*)&As[(mq + 48) * 20 + k];
            ulonglong2 b0 = *(const ulonglong2*)&Ts[(nq) * 20 + k];
            ulonglong2 b1 = *(const ulonglong2*)&Ts[(nq + 8) * 20 + k];
            ulonglong2 b2 = *(const ulonglong2*)&Ts[(nq + 16) * 20 + k];
            ulonglong2 b3 = *(const ulonglong2*)&Ts[(nq + 24) * 20 + k];
            fma2(acc[0][0], a0.x, b0.x); fma2(acc[0][0], a0.y, b0.y);
            fma2(acc[0][1], a0.x, b1.x); fma2(acc[0][1], a0.y, b1.y);
            fma2(acc[0][2], a0.x, b2.x); fma2(acc[0][2], a0.y, b2.y);
            fma2(acc[0][3], a0.x, b3.x); fma2(acc[0][3], a0.y, b3.y);
            fma2(acc[1][0], a1.x, b0.x); fma2(acc[1][0], a1.y, b0.y);
            fma2(acc[1][1], a1.x, b1.x); fma2(acc[1][1], a1.y, b1.y);
            fma2(acc[1][2], a1.x, b2.x); fma2(acc[1][2], a1.y, b2.y);
            fma2(acc[1][3], a1.x, b3.x); fma2(acc[1][3], a1.y, b3.y);
            fma2(acc[2][0], a2.x, b0.x); fma2(acc[2][0], a2.y, b0.y);
            fma2(acc[2][1], a2.x, b1.x); fma2(acc[2][1], a2.y, b1.y);
            fma2(acc[2][2], a2.x, b2.x); fma2(acc[2][2], a2.y, b2.y);
            fma2(acc[2][3], a2.x, b3.x); fma2(acc[2][3], a2.y, b3.y);
            fma2(acc[3][0], a3.x, b0.x); fma2(acc[3][0], a3.y, b0.y);
            fma2(acc[3][1], a3.x, b1.x); fma2(acc[3][1], a3.y, b1.y);
            fma2(acc[3][2], a3.x, b2.x); fma2(acc[3][2], a3.y, b2.y);
            fma2(acc[3][3], a3.x, b3.x); fma2(acc[3][3], a3.y, b3.y);
        }
        __syncthreads();
    }
#pragma unroll
    for (int i = 0; i < 4; ++i) {
        int r = rowBase + mq + 16 * i;
        int tt = r & 511, bb = r >> 9;
        float* p = out + tt * SLAB + bb * 512 + n0 + nq;
#pragma unroll
        for (int j = 0; j < 4; ++j) {
            float2 v = u2f(acc[i][j]);
            p[8 * j] = v.x + v.y;
        }
    }
}

// ---------------- Phase 2: register-B recurrence, 128 blocks ----------------
// 16 groups (4 rows) x 8 utiles (64 cols). 256 thr = 8 warps (k-split 64).
// Lane: 2 cols x 4 rows; B slice in 64 ull regs. Per-warp-private h tile
// (4 x 64, syncwarp only). Publish: stores -> bar -> tid0 st.release.gpu.
// Poll: warp 0, 8 lanes watch 8 producer flags, hard spin.
__global__ void __launch_bounds__(256, 1) p2(float* __restrict__ out,
                                             const float* __restrict__ B,
                                             const float* __restrict__ bias,
                                             const float* __restrict__ h0) {
    __shared__ float hsw[8][4 * HW];          // per-warp h tiles
    __shared__ unsigned long long red[256 * 9];

    const int tid = threadIdx.x;
    const int w = tid >> 5, lane = tid & 31;
    const int bx = blockIdx.x;      // utile 0..7
    const int g  = blockIdx.y;      // group 0..15
    const int c0 = bx * 64;
    const int rowBase = g * 4;
    const int kb = w * 64;
    const int col0 = c0 + 2 * lane;
    const int orow = tid >> 6, ocol = tid & 63;
    const float bia = bias[c0 + ocol];
    unsigned int* const myflag = &g_flag[(g * 8 + bx) * 8];
    const unsigned int* const pollflag = &g_flag[(g * 8 + (lane & 7)) * 8];
    float* const outRC = out + (size_t)(rowBase + orow) * 512 + c0 + ocol;

    // ---- one-time: B slice into registers ----
    unsigned long long b0r[32], b1r[32];
#pragma unroll
    for (int j = 0; j < 32; ++j) {
        const float* p0 = B + (kb + 2 * j) * 512 + col0;
        b0r[j] = pack2(p0[0], p0[512]);
        b1r[j] = pack2(p0[1], p0[513]);
    }

    for (int t = 0; t < NSTEP; ++t) {
        float xv = __ldcg(outRC + (size_t)t * SLAB);   // xT term prefetch

        if (t > 0) {
            if (w == 0) {   // polling warp: lanes 0..7 watch the 8 producers
                for (;;) {
                    unsigned int v = 0;
                    asm volatile("ld.acquire.gpu.global.u32 %0, [%1];"
                                 : "=r"(v) : "l"(pollflag) : "memory");
                    if (__all_sync(0xffffffffu, lane >= 8 || v >= (unsigned int)t)) break;
                }
            }
        }
        __syncthreads();   // bar1: release warps; red WAR guard

        // per-warp h slice: 4 rows x 64 k from out[t-1] (or h0)
        float* hw = &hsw[w][0];
        if (t > 0) {
            const float* hsrc = out + (size_t)(t - 1) * SLAB + rowBase * 512 + kb;
#pragma unroll
            for (int i = 0; i < 2; ++i) {
                int u = lane + 32 * i;                 // 0..63
                int r = u >> 4, c4 = (u & 15) * 4;
                float4 v = __ldcg((const float4*)(hsrc + r * 512 + c4));
                *(float4*)&hw[r * HW + c4] = v;
            }
        } else {
#pragma unroll
            for (int i = 0; i < 2; ++i) {
                int u = lane + 32 * i;
                int r = u >> 4, c4 = (u & 15) * 4;
                *(float4*)&hw[r * HW + c4] = *(const float4*)(h0 + kb + c4);
            }
        }
        __syncwarp();

        // compute: 2 cols x 4 rows per lane; B in regs; h broadcast LDS
        unsigned long long a00 = 0, a01 = 0, a10 = 0, a11 = 0;
        unsigned long long a20 = 0, a21 = 0, a30 = 0, a31 = 0;
#pragma unroll
        for (int i = 0; i < 16; ++i) {
            int k = 4 * i;
            ulonglong2 h0v = *(const ulonglong2*)&hw[0 * HW + k];
            ulonglong2 h1v = *(const ulonglong2*)&hw[1 * HW + k];
            ulonglong2 h2v = *(const ulonglong2*)&hw[2 * HW + k];
            ulonglong2 h3v = *(const ulonglong2*)&hw[3 * HW + k];
            fma2(a00, h0v.x, b0r[2*i]); fma2(a00, h0v.y, b0r[2*i+1]);
            fma2(a01, h0v.x, b1r[2*i]); fma2(a01, h0v.y, b1r[2*i+1]);
            fma2(a10, h1v.x, b0r[2*i]); fma2(a10, h1v.y, b0r[2*i+1]);
            fma2(a11, h1v.x, b1r[2*i]); fma2(a11, h1v.y, b1r[2*i+1]);
            fma2(a20, h2v.x, b0r[2*i]); fma2(a20, h2v.y, b0r[2*i+1]);
            fma2(a21, h2v.x, b1r[2*i]); fma2(a21, h2v.y, b1r[2*i+1]);
            fma2(a30, h3v.x, b0r[2*i]); fma2(a30, h3v.y, b0r[2*i+1]);
            fma2(a31, h3v.x, b1r[2*i]); fma2(a31, h3v.y, b1r[2*i+1]);
        }

        // partials: output o = r*64 + c (c = 2*lane{,+1}), red[o*9 + w]
        red[(0 * 64 + 2 * lane) * 9 + w] = a00;  red[(0 * 64 + 2 * lane + 1) * 9 + w] = a01;
        red[(1 * 64 + 2 * lane) * 9 + w] = a10;  red[(1 * 64 + 2 * lane + 1) * 9 + w] = a11;
        red[(2 * 64 + 2 * lane) * 9 + w] = a20;  red[(2 * 64 + 2 * lane + 1) * 9 + w] = a21;
        red[(3 * 64 + 2 * lane) * 9 + w] = a30;  red[(3 * 64 + 2 * lane + 1) * 9 + w] = a31;
        __syncthreads();   // bar2: partials visible

        {
            const unsigned long long* rp = red + tid * 9;
            unsigned long long s = rp[0];
#pragma unroll
            for (int ww = 1; ww < 8; ++ww) add2(s, s, rp[ww]);
            float2 p = u2f(s);
            float z = p.x + p.y + xv;
            float a = fabsf(z) + bia;
            float r = (a > 0.f) ? copysignf(a, z) : 0.f;
            __stcg(outRC + (size_t)t * SLAB, r);
        }
        __syncthreads();   // bar3: all stores program-ordered before release
        if (tid == 0) {
            asm volatile("st.release.gpu.global.u32 [%0], %1;"
                         :: "l"(myflag), "r"((unsigned int)(t + 1)) : "memory");
        }
    }
}

extern "C" void kernel_launch(void* const* d_in, const int* in_sizes, int n_in,
                              void* d_out, int out_size) {
    const float* x    = (const float*)d_in[0];
    const float* T    = (const float*)d_in[1];
    const float* B    = (const float*)d_in[2];
    const float* bias = (const float*)d_in[3];
    const float* h0   = (const float*)d_in[4];
    float* out = (float*)d_out;

    dim3 g1(512, 16);
    p1<<<g1, 128>>>(x, T, out);

    dim3 g2(8, 16);   // 8 utiles x 16 groups = 128 blocks
    p2<<<g2, 256>>>(out, B, bias, h0);
}